// round 13
// baseline (speedup 1.0000x reference)
#include <cuda_runtime.h>
#include <cuda_fp16.h>
#include <cstdint>

#define Nn 4
#define Pp 2048
#define Dd 512
#define Hh 8
#define HD 64
// sqrt(1/sqrt(512) * log2(e)) — folded into both q and k so QK^T lands in log2 domain
#define SQS 0.25250490f

// ---- scratch (__device__ globals; no allocations allowed) ----
__device__ __half g_q[Nn * Hh * Pp * HD];
__device__ __half g_k[Nn * Hh * Pp * HD];
__device__ __half g_v[Nn * Hh * Pp * HD];
__device__ __half g_E[(size_t)Nn * Hh * Pp * Pp];   // unnormalized exp, fp16
__device__ __half g_oh[Nn * Pp * Dd];
__device__ __half g_woT[Dd * Dd];
__device__ float g_inv[Nn * Hh * Pp];

// ---- helpers ----
static __device__ __forceinline__ uint32_t s2u(const void* p) {
    uint32_t a;
    asm("{ .reg .u64 t; cvta.to.shared.u64 t, %1; cvt.u32.u64 %0, t; }" : "=r"(a) : "l"(p));
    return a;
}
static __device__ __forceinline__ void ldsm4(uint32_t* r, uint32_t a) {
    asm volatile("ldmatrix.sync.aligned.m8n8.x4.shared.b16 {%0,%1,%2,%3}, [%4];"
                 : "=r"(r[0]), "=r"(r[1]), "=r"(r[2]), "=r"(r[3]) : "r"(a));
}
static __device__ __forceinline__ void ldsm4t(uint32_t* r, uint32_t a) {
    asm volatile("ldmatrix.sync.aligned.m8n8.x4.trans.shared.b16 {%0,%1,%2,%3}, [%4];"
                 : "=r"(r[0]), "=r"(r[1]), "=r"(r[2]), "=r"(r[3]) : "r"(a));
}
static __device__ __forceinline__ void mma16816(float* c, const uint32_t* a,
                                                uint32_t b0, uint32_t b1) {
    asm volatile(
        "mma.sync.aligned.m16n8k16.row.col.f32.f16.f16.f32 "
        "{%0,%1,%2,%3}, {%4,%5,%6,%7}, {%8,%9}, {%0,%1,%2,%3};"
        : "+f"(c[0]), "+f"(c[1]), "+f"(c[2]), "+f"(c[3])
        : "r"(a[0]), "r"(a[1]), "r"(a[2]), "r"(a[3]), "r"(b0), "r"(b1));
}
// 2^t via MUFU
static __device__ __forceinline__ float ex2m(float t) {
    float r;
    asm("ex2.approx.f32 %0, %1;" : "=f"(r) : "f"(t));
    return r;
}
static __device__ __forceinline__ void cpasync16(uint32_t s, const void* g) {
    asm volatile("cp.async.cg.shared.global [%0], [%1], 16;" :: "r"(s), "l"(g));
}
#define CP_COMMIT() asm volatile("cp.async.commit_group;" ::: "memory")
#define CP_WAIT0()  asm volatile("cp.async.wait_group 0;" ::: "memory")
#define CP_WAIT1()  asm volatile("cp.async.wait_group 1;" ::: "memory")

// ---- Kernel 1: QKV projection -> fp16 (q,k prescaled into log2 domain) --
__global__ void qkv_kernel(const float* __restrict__ x,
                           const float* __restrict__ Wq,
                           const float* __restrict__ Wk,
                           const float* __restrict__ Wv) {
    extern __shared__ float sq[];
    float* wq_s = sq;
    float* wk_s = wq_s + 64 * 65;
    float* wv_s = wk_s + 64 * 65;
    float* xs   = wv_s + 64 * 65;

    int t = threadIdx.x;
    for (int idx = t; idx < 4096; idx += 256) {
        int e = idx >> 6, d = idx & 63;
        wq_s[e * 65 + d] = Wq[idx];
        wk_s[e * 65 + d] = Wk[idx];
        wv_s[e * 65 + d] = Wv[idx];
    }
    size_t R0 = (size_t)blockIdx.x * 32;
    const float4* xg = (const float4*)(x + R0 * 64);
    float4* xs4 = (float4*)xs;
    xs4[t]       = xg[t];
    xs4[t + 256] = xg[t + 256];
    __syncthreads();

    int w = t >> 5, l = t & 31;
    float aq[4][2] = {}, ak[4][2] = {}, av[4][2] = {};
#pragma unroll 4
    for (int d = 0; d < 64; d++) {
        float xv[4];
#pragma unroll
        for (int i = 0; i < 4; i++) xv[i] = xs[(w * 4 + i) * 64 + d];
        float q0 = wq_s[l * 65 + d], q1 = wq_s[(l + 32) * 65 + d];
        float k0 = wk_s[l * 65 + d], k1 = wk_s[(l + 32) * 65 + d];
        float v0 = wv_s[l * 65 + d], v1 = wv_s[(l + 32) * 65 + d];
#pragma unroll
        for (int i = 0; i < 4; i++) {
            aq[i][0] += xv[i] * q0; aq[i][1] += xv[i] * q1;
            ak[i][0] += xv[i] * k0; ak[i][1] += xv[i] * k1;
            av[i][0] += xv[i] * v0; av[i][1] += xv[i] * v1;
        }
    }
#pragma unroll
    for (int i = 0; i < 4; i++) {
        int R = (int)R0 + w * 4 + i;
        int n = R / (Pp * Hh);
        int rem = R % (Pp * Hh);
        int p = rem / Hh, h = rem % Hh;
        size_t base = ((size_t)(n * Hh + h) * Pp + p) * HD;
#pragma unroll
        for (int c = 0; c < 2; c++) {
            size_t ix = base + l + c * 32;
            g_q[ix] = __float2half_rn(aq[i][c] * SQS);
            g_k[ix] = __float2half_rn(ak[i][c] * SQS);
            g_v[ix] = __float2half_rn(av[i][c]);
        }
    }
}

// ---- Kernel 2: fused HMMA attention (128 q-rows/CTA, cp.async pipeline) --
#define SROW 72
#define BUFH (128 * SROW)   // halves per K or V buffer

__global__ void __launch_bounds__(256, 2) attn_hmma_kernel() {
    extern __shared__ __half sh[];
    // layout: [buf0K | buf0V | buf1K | buf1V]
    int t = threadIdx.x;
    int w = t >> 5, l = t & 31;
    int bx = blockIdx.x;
    int qt = bx & 15, h = (bx >> 4) & 7, n = bx >> 7;
    int nh = n * Hh + h;
    int q0 = qt * 128;
    int g = l >> 2, tq = l & 3;

    uint32_t sbase = s2u(sh);

    // ---- stage Q tile (128 rows) into buf0 K area, build A-frags ----
    {
        const __half* qh = g_q + ((size_t)nh * Pp + q0) * HD;
#pragma unroll
        for (int i = 0; i < 4; i++) {
            int idx = t + i * 256;
            int row = idx >> 3, cg = idx & 7;
            *(uint4*)(sh + row * SROW + cg * 8) = *(const uint4*)(qh + row * 64 + cg * 8);
        }
    }
    __syncthreads();
    uint32_t qf[4][4];
    {
        int arow = w * 16 + (l & 7) + ((l >> 3) & 1) * 8;
        int acol = (l >> 4) * 8;
#pragma unroll
        for (int s = 0; s < 4; s++)
            ldsm4(qf[s], sbase + (uint32_t)((arow * SROW + s * 16 + acol) * 2));
    }
    __syncthreads();

    const __half* kg = g_k + (size_t)nh * Pp * HD;
    const __half* vg = g_v + (size_t)nh * Pp * HD;

    // preload chunk 0 into buffer 0
    {
        uint32_t sK = sbase, sV = sbase + BUFH * 2;
#pragma unroll
        for (int i = 0; i < 4; i++) {
            int idx = t + i * 256;
            int row = idx >> 3, cg = idx & 7;
            uint32_t so = (uint32_t)((row * SROW + cg * 8) * 2);
            size_t go = (size_t)row * 64 + cg * 8;
            cpasync16(sK + so, kg + go);
            cpasync16(sV + so, vg + go);
        }
    }
    CP_COMMIT();

    float dacc[8][4];
#pragma unroll
    for (int i = 0; i < 8; i++)
#pragma unroll
        for (int j = 0; j < 4; j++) dacc[i][j] = 0.0f;
    float rs0 = 0.0f, rs1 = 0.0f;

    int rowE0 = q0 + w * 16 + g;
    __half* eslab = g_E + (size_t)nh * Pp * (size_t)Pp;

    for (int c = 0; c < 16; c++) {
        int cb = c & 1;
        uint32_t bK = sbase + (uint32_t)(cb * 2 * BUFH * 2);
        uint32_t bV = bK + (uint32_t)(BUFH * 2);

        // prefetch chunk c+1 into the other buffer
        if (c < 15) {
            int c1 = (c + 1) * 128;
            uint32_t pK = sbase + (uint32_t)((cb ^ 1) * 2 * BUFH * 2);
            uint32_t pV = pK + (uint32_t)(BUFH * 2);
#pragma unroll
            for (int i = 0; i < 4; i++) {
                int idx = t + i * 256;
                int row = idx >> 3, cg = idx & 7;
                uint32_t so = (uint32_t)((row * SROW + cg * 8) * 2);
                size_t go = (size_t)(c1 + row) * 64 + cg * 8;
                cpasync16(pK + so, kg + go);
                cpasync16(pV + so, vg + go);
            }
            CP_COMMIT();
            CP_WAIT1();
        } else {
            CP_WAIT0();
        }
        __syncthreads();

        int c0 = c * 128;
#pragma unroll
        for (int nhf = 0; nhf < 2; nhf++) {
            // ---- QK^T for 64 kv cols ----
            float cc[8][4];
#pragma unroll
            for (int i = 0; i < 8; i++)
#pragma unroll
                for (int j2 = 0; j2 < 4; j2++) cc[i][j2] = 0.0f;

#pragma unroll
            for (int j = 0; j < 8; j++) {
                int lrow = nhf * 64 + j * 8 + (l & 7);
                int lcol = ((l >> 3) & 3) * 8;
                uint32_t off = (uint32_t)((lrow * SROW + lcol) * 2);
                uint32_t kh[4], kh2[4];
                ldsm4(kh, bK + off);
                ldsm4(kh2, bK + off + 64);
#pragma unroll
                for (int s = 0; s < 4; s++) {
                    uint32_t b0 = (s < 2) ? kh[(s & 1) * 2]     : kh2[(s & 1) * 2];
                    uint32_t b1 = (s < 2) ? kh[(s & 1) * 2 + 1] : kh2[(s & 1) * 2 + 1];
                    mma16816(cc[j], qf[s], b0, b1);
                }
            }

            // ---- exp epilogue: fp16 E store + P frags ----
            uint32_t pf[4][4];
#pragma unroll
            for (int j = 0; j < 8; j++) {
                float v0 = ex2m(cc[j][0]);
                float v1 = ex2m(cc[j][1]);
                float v2 = ex2m(cc[j][2]);
                float v3 = ex2m(cc[j][3]);
                rs0 += v0 + v1;
                rs1 += v2 + v3;
                __half2 h01 = __floats2half2_rn(v0, v1);
                __half2 h23 = __floats2half2_rn(v2, v3);
                int col = c0 + nhf * 64 + j * 8 + 2 * tq;
                *(__half2*)(eslab + (size_t)rowE0 * Pp + col)       = h01;
                *(__half2*)(eslab + (size_t)(rowE0 + 8) * Pp + col) = h23;
                int s = j >> 1, rp = (j & 1) * 2;
                pf[s][rp]     = *(uint32_t*)&h01;
                pf[s][rp + 1] = *(uint32_t*)&h23;
            }

            // ---- AV accumulate (P fp16 x V fp16) ----
#pragma unroll
            for (int s = 0; s < 4; s++) {
                int lrow = nhf * 64 + s * 16 + (l & 7) + ((l >> 3) & 1) * 8;
#pragma unroll
                for (int djp = 0; djp < 4; djp++) {
                    int dj = djp * 2;
                    int lcol = dj * 8 + (l >> 4) * 8;
                    uint32_t off = (uint32_t)((lrow * SROW + lcol) * 2);
                    uint32_t vh[4];
                    ldsm4t(vh, bV + off);
                    mma16816(dacc[dj],     pf[s], vh[0], vh[1]);
                    mma16816(dacc[dj + 1], pf[s], vh[2], vh[3]);
                }
            }
        }
        __syncthreads();
    }

    // ---- finalize: rowsums, inv, oh fp16 store ----
    rs0 += __shfl_xor_sync(0xffffffffu, rs0, 1);
    rs0 += __shfl_xor_sync(0xffffffffu, rs0, 2);
    rs1 += __shfl_xor_sync(0xffffffffu, rs1, 1);
    rs1 += __shfl_xor_sync(0xffffffffu, rs1, 2);
    float inv0 = 1.0f / rs0, inv1 = 1.0f / rs1;
    if (tq == 0) {
        g_inv[nh * Pp + rowE0]     = inv0;
        g_inv[nh * Pp + rowE0 + 8] = inv1;
    }
    size_t ob0 = ((size_t)n * Pp + rowE0) * Dd + h * HD;
    size_t ob1 = ((size_t)n * Pp + rowE0 + 8) * Dd + h * HD;
#pragma unroll
    for (int dj = 0; dj < 8; dj++) {
        int cold = dj * 8 + 2 * tq;
        *(__half2*)(g_oh + ob0 + cold) =
            __floats2half2_rn(dacc[dj][0] * inv0, dacc[dj][1] * inv0);
        *(__half2*)(g_oh + ob1 + cold) =
            __floats2half2_rn(dacc[dj][2] * inv1, dacc[dj][3] * inv1);
    }
}

// ---- Kernel 3a: Wo transpose -> fp16 -----------------------------------
__global__ void woT_kernel(const float* __restrict__ Wo) {
    __shared__ float tile[32][33];
    int x0 = blockIdx.x * 32, y0 = blockIdx.y * 32;
    int tx = threadIdx.x, ty = threadIdx.y;
#pragma unroll
    for (int i = 0; i < 32; i += 8)
        tile[ty + i][tx] = Wo[(size_t)(y0 + ty + i) * Dd + x0 + tx];
    __syncthreads();
#pragma unroll
    for (int i = 0; i < 32; i += 8)
        g_woT[(size_t)(x0 + ty + i) * Dd + y0 + tx] = __float2half_rn(tile[tx][ty + i]);
}

// ---- Kernel 3b: heterogeneous epilogue ---------------------------------
// blocks [0, 512): out = oh @ Wo^T + bo (fp16 HMMA, 128x64 tile, single buf)
// blocks [512, 66048): normalize fp16 E -> fp32 attention, REVERSED order
// (reads the most-recently-written E slabs first while they're L2-resident)
#define OAH (128 * SROW)   // A buffer halves
#define OBH (64 * SROW)    // B buffer halves
#define EPI_OUT_BLOCKS 512
#define EPI_NORM_BLOCKS 65536

__global__ void __launch_bounds__(256) epi_kernel(const float* __restrict__ bo,
                                                  float* __restrict__ out,
                                                  float* __restrict__ attn) {
    extern __shared__ __half se[];
    int t = threadIdx.x;

    if (blockIdx.x < EPI_OUT_BLOCKS) {
        // ---------------- out-GEMM path ----------------
        uint32_t sb = s2u(se);
        uint32_t bA = sb, bB = sb + (uint32_t)(OAH * 2);
        int w = t >> 5, l = t & 31;
        int ct = blockIdx.x & 7;
        int rt = blockIdx.x >> 3;
        int r0 = rt * 128, e0 = ct * 64;

        float dacc[8][4];
#pragma unroll
        for (int i = 0; i < 8; i++)
#pragma unroll
            for (int j = 0; j < 4; j++) dacc[i][j] = 0.0f;

        for (int kc = 0; kc < 8; kc++) {
            if (kc) __syncthreads();   // previous iter's reads done before overwrite
            int k0 = kc * 64;
#pragma unroll
            for (int i = 0; i < 4; i++) {
                int idx = t + i * 256;
                int row = idx >> 3, cg = (idx & 7) * 8;
                cpasync16(bA + (uint32_t)((row * SROW + cg) * 2),
                          g_oh + (size_t)(r0 + row) * Dd + k0 + cg);
            }
#pragma unroll
            for (int i = 0; i < 2; i++) {
                int idx = t + i * 256;
                int row = idx >> 3, cg = (idx & 7) * 8;
                cpasync16(bB + (uint32_t)((row * SROW + cg) * 2),
                          g_woT + (size_t)(k0 + row) * Dd + e0 + cg);
            }
            CP_COMMIT();
            CP_WAIT0();
            __syncthreads();

            uint32_t af[4][4];
            int arow = w * 16 + (l & 7) + ((l >> 3) & 1) * 8;
            int acol = (l >> 4) * 8;
#pragma unroll
            for (int s = 0; s < 4; s++)
                ldsm4(af[s], bA + (uint32_t)((arow * SROW + s * 16 + acol) * 2));
#pragma unroll
            for (int s = 0; s < 4; s++) {
                int lrow = s * 16 + (l & 7) + ((l >> 3) & 1) * 8;
#pragma unroll
                for (int djp = 0; djp < 4; djp++) {
                    int dj = djp * 2;
                    int lcol = dj * 8 + (l >> 4) * 8;
                    uint32_t bh[4];
                    ldsm4t(bh, bB + (uint32_t)((lrow * SROW + lcol) * 2));
                    mma16816(dacc[dj],     af[s], bh[0], bh[1]);
                    mma16816(dacc[dj + 1], af[s], bh[2], bh[3]);
                }
            }
        }

        int g = l >> 2, tq = l & 3;
        int row0 = r0 + w * 16 + g, row1 = row0 + 8;
#pragma unroll
        for (int dj = 0; dj < 8; dj++) {
            int col = e0 + dj * 8 + 2 * tq;
            float2 bias = *(const float2*)(bo + col);
            *(float2*)(out + (size_t)row0 * Dd + col) =
                make_float2(dacc[dj][0] + bias.x, dacc[dj][1] + bias.y);
            *(float2*)(out + (size_t)row1 * Dd + col) =
                make_float2(dacc[dj][2] + bias.x, dacc[dj][3] + bias.y);
        }
    } else {
        // ---------------- norm path (reversed block order) ----------------
        size_t bid = (size_t)(gridDim.x - 1 - blockIdx.x);  // 65535 .. 0
        size_t i = (bid * 256 + t) * 8;
        float inv = g_inv[i >> 11];
        uint4 hraw = __ldcs((const uint4*)(g_E + i));
        __half2* hp = (__half2*)&hraw;
        float4 o0, o1;
        float2 f;
        f = __half22float2(hp[0]); o0.x = f.x * inv; o0.y = f.y * inv;
        f = __half22float2(hp[1]); o0.z = f.x * inv; o0.w = f.y * inv;
        f = __half22float2(hp[2]); o1.x = f.x * inv; o1.y = f.y * inv;
        f = __half22float2(hp[3]); o1.z = f.x * inv; o1.w = f.y * inv;
        __stcs((float4*)(attn + i), o0);
        __stcs((float4*)(attn + i + 4), o1);
    }
}

extern "C" void kernel_launch(void* const* d_in, const int* in_sizes, int n_in,
                              void* d_out, int out_size) {
    const float* xyz = (const float*)d_in[0];
    const float* Wq  = (const float*)d_in[1];
    const float* Wk  = (const float*)d_in[2];
    const float* Wv  = (const float*)d_in[3];
    const float* Wo  = (const float*)d_in[4];
    const float* bo  = (const float*)d_in[5];
    float* out  = (float*)d_out;                          // (4,2048,512)
    float* attn = (float*)d_out + (size_t)Nn * Pp * Dd;   // (4,8,2048,2048)

    static const int QKV_SMEM  = (3 * 64 * 65 + 32 * 64) * 4;
    static const int ATTN_SMEM = 4 * BUFH * 2;            // 73728 B (2 bufs x K,V)
    static const int EPI_SMEM  = (OAH + OBH) * 2;         // 27648 B (single buf)
    cudaFuncSetAttribute(qkv_kernel, cudaFuncAttributeMaxDynamicSharedMemorySize, QKV_SMEM);
    cudaFuncSetAttribute(attn_hmma_kernel, cudaFuncAttributeMaxDynamicSharedMemorySize, ATTN_SMEM);
    cudaFuncSetAttribute(epi_kernel, cudaFuncAttributeMaxDynamicSharedMemorySize, EPI_SMEM);

    woT_kernel<<<dim3(16, 16), dim3(32, 8)>>>(Wo);
    qkv_kernel<<<(Nn * Pp * Hh) / 32, 256, QKV_SMEM>>>(xyz, Wq, Wk, Wv);
    attn_hmma_kernel<<<Nn * Hh * (Pp / 128), 256, ATTN_SMEM>>>();
    epi_kernel<<<EPI_OUT_BLOCKS + EPI_NORM_BLOCKS, 256, EPI_SMEM>>>(bo, out, attn);
}

// round 15
// speedup vs baseline: 1.0203x; 1.0203x over previous
#include <cuda_runtime.h>
#include <cuda_fp16.h>
#include <cstdint>

#define Nn 4
#define Pp 2048
#define Dd 512
#define Hh 8
#define HD 64
// sqrt(1/sqrt(512) * log2(e)) — folded into both q and k so QK^T lands in log2 domain
#define SQS 0.25250490f

// ---- scratch (__device__ globals; no allocations allowed) ----
__device__ __half g_q[Nn * Hh * Pp * HD];
__device__ __half g_k[Nn * Hh * Pp * HD];
__device__ __half g_v[Nn * Hh * Pp * HD];
__device__ __half g_E[(size_t)Nn * Hh * Pp * Pp];   // unnormalized exp, fp16
__device__ __half g_oh[Nn * Pp * Dd];
__device__ __half g_woT[Dd * Dd];
__device__ float g_inv[Nn * Hh * Pp];

// ---- helpers ----
static __device__ __forceinline__ uint32_t s2u(const void* p) {
    uint32_t a;
    asm("{ .reg .u64 t; cvta.to.shared.u64 t, %1; cvt.u32.u64 %0, t; }" : "=r"(a) : "l"(p));
    return a;
}
static __device__ __forceinline__ void ldsm4(uint32_t* r, uint32_t a) {
    asm volatile("ldmatrix.sync.aligned.m8n8.x4.shared.b16 {%0,%1,%2,%3}, [%4];"
                 : "=r"(r[0]), "=r"(r[1]), "=r"(r[2]), "=r"(r[3]) : "r"(a));
}
static __device__ __forceinline__ void ldsm4t(uint32_t* r, uint32_t a) {
    asm volatile("ldmatrix.sync.aligned.m8n8.x4.trans.shared.b16 {%0,%1,%2,%3}, [%4];"
                 : "=r"(r[0]), "=r"(r[1]), "=r"(r[2]), "=r"(r[3]) : "r"(a));
}
static __device__ __forceinline__ void mma16816(float* c, const uint32_t* a,
                                                uint32_t b0, uint32_t b1) {
    asm volatile(
        "mma.sync.aligned.m16n8k16.row.col.f32.f16.f16.f32 "
        "{%0,%1,%2,%3}, {%4,%5,%6,%7}, {%8,%9}, {%0,%1,%2,%3};"
        : "+f"(c[0]), "+f"(c[1]), "+f"(c[2]), "+f"(c[3])
        : "r"(a[0]), "r"(a[1]), "r"(a[2]), "r"(a[3]), "r"(b0), "r"(b1));
}
// 2^t via MUFU
static __device__ __forceinline__ float ex2m(float t) {
    float r;
    asm("ex2.approx.f32 %0, %1;" : "=f"(r) : "f"(t));
    return r;
}
static __device__ __forceinline__ void cpasync16(uint32_t s, const void* g) {
    asm volatile("cp.async.cg.shared.global [%0], [%1], 16;" :: "r"(s), "l"(g));
}
#define CP_COMMIT() asm volatile("cp.async.commit_group;" ::: "memory")
#define CP_WAIT0()  asm volatile("cp.async.wait_group 0;" ::: "memory")
#define CP_WAIT1()  asm volatile("cp.async.wait_group 1;" ::: "memory")

// ---- Kernel 1: QKV projection -> fp16 (q,k prescaled into log2 domain) --
__global__ void qkv_kernel(const float* __restrict__ x,
                           const float* __restrict__ Wq,
                           const float* __restrict__ Wk,
                           const float* __restrict__ Wv) {
    extern __shared__ float sq[];
    float* wq_s = sq;
    float* wk_s = wq_s + 64 * 65;
    float* wv_s = wk_s + 64 * 65;
    float* xs   = wv_s + 64 * 65;

    int t = threadIdx.x;
    for (int idx = t; idx < 4096; idx += 256) {
        int e = idx >> 6, d = idx & 63;
        wq_s[e * 65 + d] = Wq[idx];
        wk_s[e * 65 + d] = Wk[idx];
        wv_s[e * 65 + d] = Wv[idx];
    }
    size_t R0 = (size_t)blockIdx.x * 32;
    const float4* xg = (const float4*)(x + R0 * 64);
    float4* xs4 = (float4*)xs;
    xs4[t]       = xg[t];
    xs4[t + 256] = xg[t + 256];
    __syncthreads();

    int w = t >> 5, l = t & 31;
    float aq[4][2] = {}, ak[4][2] = {}, av[4][2] = {};
#pragma unroll 4
    for (int d = 0; d < 64; d++) {
        float xv[4];
#pragma unroll
        for (int i = 0; i < 4; i++) xv[i] = xs[(w * 4 + i) * 64 + d];
        float q0 = wq_s[l * 65 + d], q1 = wq_s[(l + 32) * 65 + d];
        float k0 = wk_s[l * 65 + d], k1 = wk_s[(l + 32) * 65 + d];
        float v0 = wv_s[l * 65 + d], v1 = wv_s[(l + 32) * 65 + d];
#pragma unroll
        for (int i = 0; i < 4; i++) {
            aq[i][0] += xv[i] * q0; aq[i][1] += xv[i] * q1;
            ak[i][0] += xv[i] * k0; ak[i][1] += xv[i] * k1;
            av[i][0] += xv[i] * v0; av[i][1] += xv[i] * v1;
        }
    }
#pragma unroll
    for (int i = 0; i < 4; i++) {
        int R = (int)R0 + w * 4 + i;
        int n = R / (Pp * Hh);
        int rem = R % (Pp * Hh);
        int p = rem / Hh, h = rem % Hh;
        size_t base = ((size_t)(n * Hh + h) * Pp + p) * HD;
#pragma unroll
        for (int c = 0; c < 2; c++) {
            size_t ix = base + l + c * 32;
            g_q[ix] = __float2half_rn(aq[i][c] * SQS);
            g_k[ix] = __float2half_rn(ak[i][c] * SQS);
            g_v[ix] = __float2half_rn(av[i][c]);
        }
    }
}

// ---- Kernel 2: fused HMMA attention (128 q-rows/CTA, cp.async pipeline) --
#define SROW 72
#define BUFH (128 * SROW)   // halves per K or V buffer

__global__ void __launch_bounds__(256, 2) attn_hmma_kernel() {
    extern __shared__ __half sh[];
    // layout: [buf0K | buf0V | buf1K | buf1V]
    int t = threadIdx.x;
    int w = t >> 5, l = t & 31;
    int bx = blockIdx.x;
    int qt = bx & 15, h = (bx >> 4) & 7, n = bx >> 7;
    int nh = n * Hh + h;
    int q0 = qt * 128;
    int g = l >> 2, tq = l & 3;

    uint32_t sbase = s2u(sh);

    // ---- stage Q tile (128 rows) into buf0 K area, build A-frags ----
    {
        const __half* qh = g_q + ((size_t)nh * Pp + q0) * HD;
#pragma unroll
        for (int i = 0; i < 4; i++) {
            int idx = t + i * 256;
            int row = idx >> 3, cg = idx & 7;
            *(uint4*)(sh + row * SROW + cg * 8) = *(const uint4*)(qh + row * 64 + cg * 8);
        }
    }
    __syncthreads();
    uint32_t qf[4][4];
    {
        int arow = w * 16 + (l & 7) + ((l >> 3) & 1) * 8;
        int acol = (l >> 4) * 8;
#pragma unroll
        for (int s = 0; s < 4; s++)
            ldsm4(qf[s], sbase + (uint32_t)((arow * SROW + s * 16 + acol) * 2));
    }
    __syncthreads();

    const __half* kg = g_k + (size_t)nh * Pp * HD;
    const __half* vg = g_v + (size_t)nh * Pp * HD;

    // preload chunk 0 into buffer 0
    {
        uint32_t sK = sbase, sV = sbase + BUFH * 2;
#pragma unroll
        for (int i = 0; i < 4; i++) {
            int idx = t + i * 256;
            int row = idx >> 3, cg = idx & 7;
            uint32_t so = (uint32_t)((row * SROW + cg * 8) * 2);
            size_t go = (size_t)row * 64 + cg * 8;
            cpasync16(sK + so, kg + go);
            cpasync16(sV + so, vg + go);
        }
    }
    CP_COMMIT();

    float dacc[8][4];
#pragma unroll
    for (int i = 0; i < 8; i++)
#pragma unroll
        for (int j = 0; j < 4; j++) dacc[i][j] = 0.0f;
    float rs0 = 0.0f, rs1 = 0.0f;

    int rowE0 = q0 + w * 16 + g;
    __half* eslab = g_E + (size_t)nh * Pp * (size_t)Pp;

    for (int c = 0; c < 16; c++) {
        int cb = c & 1;
        uint32_t bK = sbase + (uint32_t)(cb * 2 * BUFH * 2);
        uint32_t bV = bK + (uint32_t)(BUFH * 2);

        // prefetch chunk c+1 into the other buffer
        if (c < 15) {
            int c1 = (c + 1) * 128;
            uint32_t pK = sbase + (uint32_t)((cb ^ 1) * 2 * BUFH * 2);
            uint32_t pV = pK + (uint32_t)(BUFH * 2);
#pragma unroll
            for (int i = 0; i < 4; i++) {
                int idx = t + i * 256;
                int row = idx >> 3, cg = idx & 7;
                uint32_t so = (uint32_t)((row * SROW + cg * 8) * 2);
                size_t go = (size_t)(c1 + row) * 64 + cg * 8;
                cpasync16(pK + so, kg + go);
                cpasync16(pV + so, vg + go);
            }
            CP_COMMIT();
            CP_WAIT1();
        } else {
            CP_WAIT0();
        }
        __syncthreads();

        int c0 = c * 128;
#pragma unroll
        for (int nhf = 0; nhf < 2; nhf++) {
            // ---- QK^T for 64 kv cols ----
            float cc[8][4];
#pragma unroll
            for (int i = 0; i < 8; i++)
#pragma unroll
                for (int j2 = 0; j2 < 4; j2++) cc[i][j2] = 0.0f;

#pragma unroll
            for (int j = 0; j < 8; j++) {
                int lrow = nhf * 64 + j * 8 + (l & 7);
                int lcol = ((l >> 3) & 3) * 8;
                uint32_t off = (uint32_t)((lrow * SROW + lcol) * 2);
                uint32_t kh[4], kh2[4];
                ldsm4(kh, bK + off);
                ldsm4(kh2, bK + off + 64);
#pragma unroll
                for (int s = 0; s < 4; s++) {
                    uint32_t b0 = (s < 2) ? kh[(s & 1) * 2]     : kh2[(s & 1) * 2];
                    uint32_t b1 = (s < 2) ? kh[(s & 1) * 2 + 1] : kh2[(s & 1) * 2 + 1];
                    mma16816(cc[j], qf[s], b0, b1);
                }
            }

            // ---- exp epilogue: fp16 E store + P frags ----
            uint32_t pf[4][4];
#pragma unroll
            for (int j = 0; j < 8; j++) {
                float v0 = ex2m(cc[j][0]);
                float v1 = ex2m(cc[j][1]);
                float v2 = ex2m(cc[j][2]);
                float v3 = ex2m(cc[j][3]);
                rs0 += v0 + v1;
                rs1 += v2 + v3;
                __half2 h01 = __floats2half2_rn(v0, v1);
                __half2 h23 = __floats2half2_rn(v2, v3);
                int col = c0 + nhf * 64 + j * 8 + 2 * tq;
                *(__half2*)(eslab + (size_t)rowE0 * Pp + col)       = h01;
                *(__half2*)(eslab + (size_t)(rowE0 + 8) * Pp + col) = h23;
                int s = j >> 1, rp = (j & 1) * 2;
                pf[s][rp]     = *(uint32_t*)&h01;
                pf[s][rp + 1] = *(uint32_t*)&h23;
            }

            // ---- AV accumulate (P fp16 x V fp16) ----
#pragma unroll
            for (int s = 0; s < 4; s++) {
                int lrow = nhf * 64 + s * 16 + (l & 7) + ((l >> 3) & 1) * 8;
#pragma unroll
                for (int djp = 0; djp < 4; djp++) {
                    int dj = djp * 2;
                    int lcol = dj * 8 + (l >> 4) * 8;
                    uint32_t off = (uint32_t)((lrow * SROW + lcol) * 2);
                    uint32_t vh[4];
                    ldsm4t(vh, bV + off);
                    mma16816(dacc[dj],     pf[s], vh[0], vh[1]);
                    mma16816(dacc[dj + 1], pf[s], vh[2], vh[3]);
                }
            }
        }
        __syncthreads();
    }

    // ---- finalize: rowsums, inv, oh fp16 store ----
    rs0 += __shfl_xor_sync(0xffffffffu, rs0, 1);
    rs0 += __shfl_xor_sync(0xffffffffu, rs0, 2);
    rs1 += __shfl_xor_sync(0xffffffffu, rs1, 1);
    rs1 += __shfl_xor_sync(0xffffffffu, rs1, 2);
    float inv0 = 1.0f / rs0, inv1 = 1.0f / rs1;
    if (tq == 0) {
        g_inv[nh * Pp + rowE0]     = inv0;
        g_inv[nh * Pp + rowE0 + 8] = inv1;
    }
    size_t ob0 = ((size_t)n * Pp + rowE0) * Dd + h * HD;
    size_t ob1 = ((size_t)n * Pp + rowE0 + 8) * Dd + h * HD;
#pragma unroll
    for (int dj = 0; dj < 8; dj++) {
        int cold = dj * 8 + 2 * tq;
        *(__half2*)(g_oh + ob0 + cold) =
            __floats2half2_rn(dacc[dj][0] * inv0, dacc[dj][1] * inv0);
        *(__half2*)(g_oh + ob1 + cold) =
            __floats2half2_rn(dacc[dj][2] * inv1, dacc[dj][3] * inv1);
    }
}

// ---- Kernel 3: normalize fp16 E -> fp32 attention (streaming) ----------
__global__ void norm_kernel(float* __restrict__ attn) {
    size_t i = ((size_t)blockIdx.x * 256 + threadIdx.x) * 8;
    float inv = g_inv[i >> 11];
    uint4 hraw = __ldcs((const uint4*)(g_E + i));
    __half2* hp = (__half2*)&hraw;
    float4 o0, o1;
    float2 f;
    f = __half22float2(hp[0]); o0.x = f.x * inv; o0.y = f.y * inv;
    f = __half22float2(hp[1]); o0.z = f.x * inv; o0.w = f.y * inv;
    f = __half22float2(hp[2]); o1.x = f.x * inv; o1.y = f.y * inv;
    f = __half22float2(hp[3]); o1.z = f.x * inv; o1.w = f.y * inv;
    __stcs((float4*)(attn + i), o0);
    __stcs((float4*)(attn + i + 4), o1);
}

// ---- Kernel 4a: Wo transpose -> fp16 -----------------------------------
__global__ void woT_kernel(const float* __restrict__ Wo) {
    __shared__ float tile[32][33];
    int x0 = blockIdx.x * 32, y0 = blockIdx.y * 32;
    int tx = threadIdx.x, ty = threadIdx.y;
#pragma unroll
    for (int i = 0; i < 32; i += 8)
        tile[ty + i][tx] = Wo[(size_t)(y0 + ty + i) * Dd + x0 + tx];
    __syncthreads();
#pragma unroll
    for (int i = 0; i < 32; i += 8)
        g_woT[(size_t)(x0 + ty + i) * Dd + y0 + tx] = __float2half_rn(tile[tx][ty + i]);
}

// ---- Kernel 4b: out = oh @ Wo^T + bo (fp16 HMMA) -----------------------
__global__ void __launch_bounds__(128) out_kernel(const float* __restrict__ bo,
                                                  float* __restrict__ out) {
    __shared__ __half sA[64 * SROW];
    __shared__ __half sB[64 * SROW];
    uint32_t bA = s2u(sA), bB = s2u(sB);

    int t = threadIdx.x;
    int w = t >> 5, l = t & 31;
    int ct = blockIdx.x & 7;
    int rt = blockIdx.x >> 3;
    int r0 = rt * 64, e0 = ct * 64;

    float dacc[8][4];
#pragma unroll
    for (int i = 0; i < 8; i++)
#pragma unroll
        for (int j = 0; j < 4; j++) dacc[i][j] = 0.0f;

    for (int kc = 0; kc < Dd; kc += 64) {
        __syncthreads();
#pragma unroll
        for (int i = 0; i < 4; i++) {
            int idx = t + i * 128;
            int row = idx >> 3, cg = (idx & 7) * 8;
            int so = row * SROW + cg;
            *(uint4*)(sA + so) = *(const uint4*)(g_oh + (size_t)(r0 + row) * Dd + kc + cg);
            *(uint4*)(sB + so) = *(const uint4*)(g_woT + (size_t)(kc + row) * Dd + e0 + cg);
        }
        __syncthreads();

        uint32_t af[4][4];
        int arow = w * 16 + (l & 7) + ((l >> 3) & 1) * 8;
        int acol = (l >> 4) * 8;
#pragma unroll
        for (int s = 0; s < 4; s++) {
            uint32_t off = (uint32_t)((arow * SROW + s * 16 + acol) * 2);
            ldsm4(af[s], bA + off);
        }
#pragma unroll
        for (int s = 0; s < 4; s++) {
            int lrow = s * 16 + (l & 7) + ((l >> 3) & 1) * 8;
#pragma unroll
            for (int djp = 0; djp < 4; djp++) {
                int dj = djp * 2;
                int lcol = dj * 8 + (l >> 4) * 8;
                uint32_t off = (uint32_t)((lrow * SROW + lcol) * 2);
                uint32_t bh[4];
                ldsm4t(bh, bB + off);
                mma16816(dacc[dj],     af[s], bh[0], bh[1]);
                mma16816(dacc[dj + 1], af[s], bh[2], bh[3]);
            }
        }
    }

    int g = l >> 2, tq = l & 3;
    int row0 = r0 + w * 16 + g, row1 = row0 + 8;
#pragma unroll
    for (int dj = 0; dj < 8; dj++) {
        int col = e0 + dj * 8 + 2 * tq;
        float2 bias = *(const float2*)(bo + col);
        *(float2*)(out + (size_t)row0 * Dd + col) =
            make_float2(dacc[dj][0] + bias.x, dacc[dj][1] + bias.y);
        *(float2*)(out + (size_t)row1 * Dd + col) =
            make_float2(dacc[dj][2] + bias.x, dacc[dj][3] + bias.y);
    }
}

// ---- stream/event singletons: created on the FIRST (correctness) call,
// i.e. BEFORE graph capture begins; capture only sees record/wait ops. ----
struct SideStream {
    cudaStream_t s;
    cudaEvent_t ev_fork, ev_attn, ev_join;
    SideStream() {
        cudaStreamCreateWithFlags(&s, cudaStreamNonBlocking);
        cudaEventCreateWithFlags(&ev_fork, cudaEventDisableTiming);
        cudaEventCreateWithFlags(&ev_attn, cudaEventDisableTiming);
        cudaEventCreateWithFlags(&ev_join, cudaEventDisableTiming);
    }
};

extern "C" void kernel_launch(void* const* d_in, const int* in_sizes, int n_in,
                              void* d_out, int out_size) {
    const float* xyz = (const float*)d_in[0];
    const float* Wq  = (const float*)d_in[1];
    const float* Wk  = (const float*)d_in[2];
    const float* Wv  = (const float*)d_in[3];
    const float* Wo  = (const float*)d_in[4];
    const float* bo  = (const float*)d_in[5];
    float* out  = (float*)d_out;                          // (4,2048,512)
    float* attn = (float*)d_out + (size_t)Nn * Pp * Dd;   // (4,8,2048,2048)

    static SideStream ss;   // constructed during the pre-capture correctness call

    static const int QKV_SMEM  = (3 * 64 * 65 + 32 * 64) * 4;
    static const int ATTN_SMEM = 4 * BUFH * 2;            // 73728 B (2 bufs x K,V)
    cudaFuncSetAttribute(qkv_kernel, cudaFuncAttributeMaxDynamicSharedMemorySize, QKV_SMEM);
    cudaFuncSetAttribute(attn_hmma_kernel, cudaFuncAttributeMaxDynamicSharedMemorySize, ATTN_SMEM);

    // fork side stream off the main stream
    cudaEventRecord(ss.ev_fork, 0);
    cudaStreamWaitEvent(ss.s, ss.ev_fork, 0);

    // side stream: Wo transpose (independent of qkv/attn)
    woT_kernel<<<dim3(16, 16), dim3(32, 8), 0, ss.s>>>(Wo);

    // main stream: qkv -> attn
    qkv_kernel<<<(Nn * Pp * Hh) / 32, 256, QKV_SMEM>>>(xyz, Wq, Wk, Wv);
    attn_hmma_kernel<<<Nn * Hh * (Pp / 128), 256, ATTN_SMEM>>>();

    // after attn: out (side stream) runs CONCURRENTLY with norm (main stream)
    cudaEventRecord(ss.ev_attn, 0);
    cudaStreamWaitEvent(ss.s, ss.ev_attn, 0);
    out_kernel<<<(Nn * Pp / 64) * (Dd / 64), 128, 0, ss.s>>>(bo, out);
    cudaEventRecord(ss.ev_join, ss.s);

    norm_kernel<<<(int)(((size_t)Nn * Hh * Pp * Pp) / 8 / 256), 256>>>(attn);

    // join side stream back into the main stream
    cudaStreamWaitEvent(0, ss.ev_join, 0);
}